// round 16
// baseline (speedup 1.0000x reference)
#include <cuda_runtime.h>
#include <cuda_fp16.h>
#include <cstdint>

// Problem constants
#define B_DIM   512
#define QB      128             // batch rows per quarter
#define IN_DIM  65536
#define OUT_DIM 16384
#define K_DIM   32
#define OTILE   16              // outputs per gather block

#define TBLK_Q  2048            // transpose tiles per quarter (1024 in x 2 bands)
#define GBLK_Q  1024            // gather blocks per quarter (16384/16)
#define GRID_TOTAL (4 * TBLK_Q + 4 * GBLK_Q)   // 12288

// 64 MB scratch for transposed x in fp16: xt[in][b]
__device__ __half g_xt_h[(size_t)IN_DIM * B_DIM];

// Gating state. Zero at load; the LAST gather block to pass its gate zeroes
// everything for the next graph replay.
__device__ int g_tdone[4];
__device__ int g_gpassed;

// Bit-reinterpretation helpers
__device__ __forceinline__ unsigned int h2_to_u32(__half2 h) {
    union { __half2 h; unsigned int u; } c; c.h = h; return c.u;
}
__device__ __forceinline__ float2 u32_to_f2(unsigned int u) {
    union { unsigned int u; __half2 h; } c; c.u = u;
    return __half22float2(c.h);
}

// Shared-memory shapes (union -> fused footprint = max, not sum)
struct SmemT {
    float4 tile4[64][17];                      // 64b x 64in tile, padded
};
struct SmemG {
    int4   sidx4[OTILE][K_DIM / 4];
    float4 sw4[OTILE][K_DIM / 4];
    float  sbias[OTILE];
    float  sout[OTILE][QB + 4];                // [o][b-local]
};
union SmemU { SmemT t; SmemG g; };

// ---------------------------------------------------------------------------
// Transpose tile body: 64 b-rows x 64 in-cols of x -> fp16 xt.
// ---------------------------------------------------------------------------
__device__ __forceinline__ void transpose_tile(
    const float* __restrict__ x, int in0, int b0, int q, SmemT& s)
{
    const int t = threadIdx.x;

    const int c4 = t & 15;                     // float4 col 0..15
    const int r0 = t >> 4;                     // 0..15
    #pragma unroll
    for (int it = 0; it < 4; it++) {
        const int r = r0 + 16 * it;            // b-row 0..63
        s.tile4[r][c4] =
            *(const float4*)&x[(size_t)(b0 + r) * IN_DIM + in0 + 4 * c4];
    }
    __syncthreads();

    const int i  = t >> 2;                     // in-row 0..63
    const int p  = t & 3;                      // 16-b chunk (32B)
    const int c  = i >> 2;
    const int cc = i & 3;

    __half2 h2[8];
    #pragma unroll
    for (int j = 0; j < 8; j++) {
        const float f0 = ((const float*)&s.tile4[16 * p + 2 * j + 0][c])[cc];
        const float f1 = ((const float*)&s.tile4[16 * p + 2 * j + 1][c])[cc];
        h2[j] = __floats2half2_rn(f0, f1);
    }
    uint4 u0, u1;
    u0.x = h2_to_u32(h2[0]); u0.y = h2_to_u32(h2[1]);
    u0.z = h2_to_u32(h2[2]); u0.w = h2_to_u32(h2[3]);
    u1.x = h2_to_u32(h2[4]); u1.y = h2_to_u32(h2[5]);
    u1.z = h2_to_u32(h2[6]); u1.w = h2_to_u32(h2[7]);

    uint4* dst = (uint4*)&g_xt_h[(size_t)(in0 + i) * B_DIM + b0 + 16 * p];
    dst[0] = u0;
    dst[1] = u1;

    __syncthreads();
    if (t == 0) {
        __threadfence();                       // release stores
        atomicAdd(&g_tdone[q], 1);
    }
}

// ---------------------------------------------------------------------------
// Gather block body: 16 outputs x one b-quarter. Warp handles TWO outputs:
// lanes 0-15 -> output 2*wo, lanes 16-31 -> 2*wo+1. Each lane: 8 b-rows via
// LDG.128 per (o,k). SOFTWARE PIPELINE: group i+1's 4 loads issue before
// group i's convert+FMA -> 8 independent LDG.128 in flight steady-state.
// ---------------------------------------------------------------------------
__device__ __forceinline__ void gather_block(
    const int*   __restrict__ idx,
    const float* __restrict__ w,
    const float* __restrict__ bias,
    float*       __restrict__ out,
    int q, int o0, SmemG& s)
{
    const int tid = threadIdx.x;
    const int wo  = tid >> 5;                  // warp 0..7
    const int l   = tid & 31;
    const int oo  = 2 * wo + (l >> 4);         // this lane's output 0..15
    const int ls  = l & 15;                    // lane-slot within output

    // Stage idx/w/bias (256 threads cover 128 int4 + 128 float4)
    if (tid < 128) {
        s.sidx4[tid >> 3][tid & 7] =
            ((const int4*)idx)[(size_t)(o0 + (tid >> 3)) * 8 + (tid & 7)];
        if (tid < OTILE) s.sbias[tid] = bias[o0 + tid];
    } else {
        const int u = tid - 128;
        s.sw4[u >> 3][u & 7] =
            ((const float4*)w)[(size_t)(o0 + (u >> 3)) * 8 + (u & 7)];
    }

    // Acquire: wait until this quarter's transpose fully arrived.
    if (tid == 0) {
        while (*(volatile int*)&g_tdone[q] < TBLK_Q) __nanosleep(64);
        __threadfence();
        const int old = atomicAdd(&g_gpassed, 1);
        if (old == 4 * GBLK_Q - 1) {
            g_tdone[0] = 0; g_tdone[1] = 0;
            g_tdone[2] = 0; g_tdone[3] = 0;
            g_gpassed  = 0;
        }
    }
    __syncthreads();

    // xt row = 512 halves = 64 uint4 slots; quarter q = slots [16q, 16q+16).
    const uint4* __restrict__ xt16 =
        reinterpret_cast<const uint4*>(g_xt_h) + (size_t)q * 16 + ls;

    float a0 = 0.f, a1 = 0.f, a2 = 0.f, a3 = 0.f;
    float a4 = 0.f, a5 = 0.f, a6 = 0.f, a7 = 0.f;

    // Prologue: issue group 0's loads.
    uint4 v0, v1, v2, v3;
    {
        const int4 ii = s.sidx4[oo][0];
        v0 = __ldg(&xt16[(size_t)ii.x * 64]);
        v1 = __ldg(&xt16[(size_t)ii.y * 64]);
        v2 = __ldg(&xt16[(size_t)ii.z * 64]);
        v3 = __ldg(&xt16[(size_t)ii.w * 64]);
    }

    #pragma unroll
    for (int k4 = 0; k4 < K_DIM / 4; k4++) {
        // Issue next group's loads BEFORE consuming this group's data.
        uint4 n0, n1, n2, n3;
        if (k4 < K_DIM / 4 - 1) {
            const int4 jj = s.sidx4[oo][k4 + 1];
            n0 = __ldg(&xt16[(size_t)jj.x * 64]);
            n1 = __ldg(&xt16[(size_t)jj.y * 64]);
            n2 = __ldg(&xt16[(size_t)jj.z * 64]);
            n3 = __ldg(&xt16[(size_t)jj.w * 64]);
        }

        const float4 ww = s.sw4[oo][k4];
        {
            const float2 f0 = u32_to_f2(v0.x), f1 = u32_to_f2(v0.y);
            const float2 f2 = u32_to_f2(v0.z), f3 = u32_to_f2(v0.w);
            a0 += f0.x * ww.x; a1 += f0.y * ww.x;
            a2 += f1.x * ww.x; a3 += f1.y * ww.x;
            a4 += f2.x * ww.x; a5 += f2.y * ww.x;
            a6 += f3.x * ww.x; a7 += f3.y * ww.x;
        }
        {
            const float2 f0 = u32_to_f2(v1.x), f1 = u32_to_f2(v1.y);
            const float2 f2 = u32_to_f2(v1.z), f3 = u32_to_f2(v1.w);
            a0 += f0.x * ww.y; a1 += f0.y * ww.y;
            a2 += f1.x * ww.y; a3 += f1.y * ww.y;
            a4 += f2.x * ww.y; a5 += f2.y * ww.y;
            a6 += f3.x * ww.y; a7 += f3.y * ww.y;
        }
        {
            const float2 f0 = u32_to_f2(v2.x), f1 = u32_to_f2(v2.y);
            const float2 f2 = u32_to_f2(v2.z), f3 = u32_to_f2(v2.w);
            a0 += f0.x * ww.z; a1 += f0.y * ww.z;
            a2 += f1.x * ww.z; a3 += f1.y * ww.z;
            a4 += f2.x * ww.z; a5 += f2.y * ww.z;
            a6 += f3.x * ww.z; a7 += f3.y * ww.z;
        }
        {
            const float2 f0 = u32_to_f2(v3.x), f1 = u32_to_f2(v3.y);
            const float2 f2 = u32_to_f2(v3.z), f3 = u32_to_f2(v3.w);
            a0 += f0.x * ww.w; a1 += f0.y * ww.w;
            a2 += f1.x * ww.w; a3 += f1.y * ww.w;
            a4 += f2.x * ww.w; a5 += f2.y * ww.w;
            a6 += f3.x * ww.w; a7 += f3.y * ww.w;
        }

        if (k4 < K_DIM / 4 - 1) {
            v0 = n0; v1 = n1; v2 = n2; v3 = n3;   // renamed away (full unroll)
        }
    }

    const float bv = s.sbias[oo];
    float4 s0 = make_float4(a0 + bv, a1 + bv, a2 + bv, a3 + bv);
    float4 s1 = make_float4(a4 + bv, a5 + bv, a6 + bv, a7 + bv);
    *(float4*)&s.sout[oo][8 * ls + 0] = s0;
    *(float4*)&s.sout[oo][8 * ls + 4] = s1;
    __syncthreads();

    // Coalesced out store: threads 0..127 own b = q*128 + tid, write
    // out[b][o0..o0+15] as four STG.128.
    if (tid < QB) {
        const int b = q * QB + tid;
        float4 r0, r1, r2, r3;
        r0.x = s.sout[ 0][tid]; r0.y = s.sout[ 1][tid];
        r0.z = s.sout[ 2][tid]; r0.w = s.sout[ 3][tid];
        r1.x = s.sout[ 4][tid]; r1.y = s.sout[ 5][tid];
        r1.z = s.sout[ 6][tid]; r1.w = s.sout[ 7][tid];
        r2.x = s.sout[ 8][tid]; r2.y = s.sout[ 9][tid];
        r2.z = s.sout[10][tid]; r2.w = s.sout[11][tid];
        r3.x = s.sout[12][tid]; r3.y = s.sout[13][tid];
        r3.z = s.sout[14][tid]; r3.w = s.sout[15][tid];
        float4* dst = reinterpret_cast<float4*>(out + (size_t)b * OUT_DIM + o0);
        dst[0] = r0; dst[1] = r1; dst[2] = r2; dst[3] = r3;
    }
}

// ---------------------------------------------------------------------------
// Mega kernel (R15 schedule, grid exactly 12288):
//   [0,2048):          T(q0)
//   3 phases of 3072:  2:1  T(q+1) : G(q)
//   [11264,12288):     G(q3)
// Deadlock-free: every T(q) bid precedes every G(q) bid; CTAs are claimed in
// bid order, so gated counters always reach TBLK_Q.
// ---------------------------------------------------------------------------
__global__ __launch_bounds__(256) void mega_kernel(
    const float* __restrict__ x,
    const int*   __restrict__ idx,
    const float* __restrict__ w,
    const float* __restrict__ bias,
    float*       __restrict__ out)
{
    __shared__ SmemU sm;
    const int bx = blockIdx.x;

    if (bx < TBLK_Q) {
        const int j = bx;
        transpose_tile(x, (j & 1023) << 6, (j >> 10) << 6, 0, sm.t);
    } else if (bx < TBLK_Q + 3 * (TBLK_Q + GBLK_Q)) {
        const int r     = bx - TBLK_Q;         // 0..9215
        const int phase = r / 3072;            // 0..2
        const int off   = r - phase * 3072;
        const int grp   = off / 3;             // 0..1023
        const int rem   = off - 3 * grp;
        if (rem < 2) {
            const int q = phase + 1;
            const int j = 2 * grp + rem;       // 0..2047
            transpose_tile(x, (j & 1023) << 6,
                           q * QB + ((j >> 10) << 6), q, sm.t);
        } else {
            gather_block(idx, w, bias, out, phase, grp * OTILE, sm.g);
        }
    } else {
        const int j = bx - (TBLK_Q + 3 * (TBLK_Q + GBLK_Q));
        gather_block(idx, w, bias, out, 3, j * OTILE, sm.g);
    }
}

// ---------------------------------------------------------------------------
// Launch: single kernel, self-resetting via last-gate-passer.
// ---------------------------------------------------------------------------
extern "C" void kernel_launch(void* const* d_in, const int* in_sizes, int n_in,
                              void* d_out, int out_size) {
    const float* x    = (const float*)d_in[0];
    const int*   idx  = (const int*)  d_in[1];
    const float* w    = (const float*)d_in[2];
    const float* bias = (const float*)d_in[3];
    float*       out  = (float*)d_out;

    mega_kernel<<<GRID_TOTAL, 256>>>(x, idx, w, bias, out);
}